// round 16
// baseline (speedup 1.0000x reference)
#include <cuda_runtime.h>
#include <cuda_fp16.h>
#include <cstdint>

// ------------- weight layout: f16 mma-fragment-packed blocks (uints) -------
// Wide block (kt, np) = 128 uints: lane*4 + {b0_j0, b1_j0, b0_j1, b1_j1}
// b0 = half2{B[kt*16+2q][n], B[kt*16+2q+1][n]}, b1 = rows +8,+9; n = np*16+j*8+r
#define OFF_COL0 0          // 4 kt x 4 np
#define OFF_VIS0 2048       // 3 x 4
#define OFF_SIG0 3584       // 2 x 4
#define OFF_C1A  4608       // 4 x 4
#define OFF_C1B  6656       // 1 x 4 (k row0 zero, rows 1..15 = col1 rows 64..78)
#define OFF_SIG1 7168       // 4 kt x 1 np
#define OFF_COL2 7680       // 4 kt x 64 uints (single n8, n<3 real)
#define OFF_V1L  7936       // 64 f32 (vis1 weights, stored as bits)
#define W_TOTAL  8192

__device__ __align__(16) unsigned g_W[W_TOTAL];

__device__ void packB16(unsigned* dst, const float* W, int Kreal, int Nreal,
                        int KT, int NP, int t, int st) {
    for (int idx = t; idx < KT * NP * 128; idx += st) {
        int blk = idx >> 7, w = idx & 127;
        int lane = w >> 2, j2 = w & 3;
        int j = j2 >> 1, which = j2 & 1;
        int kt = blk / NP, np = blk % NP;
        int r = lane >> 2, q = lane & 3;
        int n = np * 16 + j * 8 + r;
        int k0 = kt * 16 + 2 * q + which * 8;
        float v0 = (k0 < Kreal && n < Nreal) ? W[k0 * Nreal + n] : 0.f;
        float v1 = (k0 + 1 < Kreal && n < Nreal) ? W[(k0 + 1) * Nreal + n] : 0.f;
        __half2 h = __floats2half2_rn(v0, v1);
        dst[idx] = *(unsigned*)&h;
    }
}

__global__ void prep_kernel(const float* __restrict__ ws0, const float* __restrict__ ws1,
                            const float* __restrict__ wc0, const float* __restrict__ wc1,
                            const float* __restrict__ wc2, const float* __restrict__ wv0,
                            const float* __restrict__ wv1) {
    int t = threadIdx.x;
    packB16(g_W + OFF_COL0, wc0, 64, 64, 4, 4, t, 256);
    packB16(g_W + OFF_VIS0, wv0, 48, 64, 3, 4, t, 256);
    packB16(g_W + OFF_SIG0, ws0, 32, 64, 2, 4, t, 256);
    packB16(g_W + OFF_C1A,  wc1, 64, 64, 4, 4, t, 256);
    packB16(g_W + OFF_SIG1, ws1, 64, 16, 4, 1, t, 256);
    // C1B: logical 16-row K block, row0 = 0, row k = wc1[(63+k)][n]
    for (int idx = t; idx < 512; idx += 256) {
        int w = idx & 127;
        int lane = w >> 2, j2 = w & 3;
        int j = j2 >> 1, which = j2 & 1;
        int np = idx >> 7;
        int r = lane >> 2, q = lane & 3;
        int n = np * 16 + j * 8 + r;
        int k0 = 2 * q + which * 8;
        float v0 = (k0 >= 1 && k0 < 16) ? wc1[(63 + k0) * 64 + n] : 0.f;
        float v1 = (k0 + 1 >= 1 && k0 + 1 < 16) ? wc1[(63 + k0 + 1) * 64 + n] : 0.f;
        __half2 h = __floats2half2_rn(v0, v1);
        g_W[OFF_C1B + idx] = *(unsigned*)&h;
    }
    // COL2: single n8 blocks, 64 uints each
    for (int idx = t; idx < 4 * 64; idx += 256) {
        int kt = idx >> 6, w = idx & 63;
        int lane = w >> 1, which = w & 1;
        int r = lane >> 2, q = lane & 3;
        int n = r;
        int k0 = kt * 16 + 2 * q + which * 8;
        float v0 = (n < 3) ? wc2[k0 * 3 + n] : 0.f;
        float v1 = (n < 3) ? wc2[(k0 + 1) * 3 + n] : 0.f;
        __half2 h = __floats2half2_rn(v0, v1);
        g_W[OFF_COL2 + idx] = *(unsigned*)&h;
    }
    for (int i = t; i < 256; i += 256) {
        g_W[OFF_V1L + i] = (i < 64) ? __float_as_uint(wv1[i]) : 0u;
    }
}

// ---------------- SH degree-4 ----------------
__device__ __forceinline__ void sh16(float x, float y, float z, float* e) {
    float xx = x * x, yy = y * y, zz = z * z;
    float xy = x * y, yz = y * z, xz = x * z;
    e[0]  = 0.28209479177387814f;
    e[1]  = -0.48860251190291987f * y;
    e[2]  = 0.48860251190291987f * z;
    e[3]  = -0.48860251190291987f * x;
    e[4]  = 1.0925484305920792f * xy;
    e[5]  = -1.0925484305920792f * yz;
    e[6]  = 0.94617469575756f * zz - 0.31539156525252005f;
    e[7]  = -1.0925484305920792f * xz;
    e[8]  = 0.5462742152960396f * (xx - yy);
    e[9]  = 0.5900435899266435f * y * (3.0f * xx - yy);
    e[10] = 2.890611442640554f * xy * z;
    e[11] = 0.4570457994644657f * y * (4.0f * zz - xx - yy);
    e[12] = 0.3731763325901154f * z * (2.0f * zz - 3.0f * xx - 3.0f * yy);
    e[13] = 0.4570457994644657f * x * (4.0f * zz - xx - yy);
    e[14] = 1.445305721320277f * z * (xx - yy);
    e[15] = 0.5900435899266435f * x * (xx - 3.0f * yy);
}

// ---- smem layout (float indices): 128-row tile (2 groups), 2 CTAs/SM -----
#define SM_B1    8192               // [128][72] halfs = 4608 floats
#define SM_B2    12800              // [128][72] halfs
#define SM_VISP  17408              // [128][2] f32
#define SM_VISR  17664              // [128] f32
#define SM_COLP  17792              // [128][16] f32
#define SM_TOTAL 19840
#define SMEM_BYTES (SM_TOTAL * 4)

// ---------------- raw f16 mma helpers ----------------
__device__ __forceinline__ void mma16(float* c, const unsigned* a, unsigned b0, unsigned b1) {
    asm volatile(
        "mma.sync.aligned.m16n8k16.row.col.f32.f16.f16.f32 "
        "{%0,%1,%2,%3}, {%4,%5,%6,%7}, {%8,%9}, {%0,%1,%2,%3};"
        : "+f"(c[0]), "+f"(c[1]), "+f"(c[2]), "+f"(c[3])
        : "r"(a[0]), "r"(a[1]), "r"(a[2]), "r"(a[3]), "r"(b0), "r"(b1));
}

__device__ __forceinline__ void loadA16(unsigned* a, const __half* Ab, int kt, int lane) {
    int r = lane >> 2, q = lane & 3;
    const __half* p = Ab + r * 72 + kt * 16 + 2 * q;
    a[0] = *(const unsigned*)(p);
    a[1] = *(const unsigned*)(p + 8 * 72);
    a[2] = *(const unsigned*)(p + 8);
    a[3] = *(const unsigned*)(p + 8 * 72 + 8);
}

__device__ __forceinline__ void storeF16(__half* dst, int row0, int cbase, int lane,
                                         float c0, float c1, float c2, float c3) {
    int r = lane >> 2, q = lane & 3;
    __half2 lo = __floats2half2_rn(c0, c1);
    __half2 hi = __floats2half2_rn(c2, c3);
    *(unsigned*)(dst + (row0 + r) * 72 + cbase + 2 * q) = *(unsigned*)&lo;
    *(unsigned*)(dst + (row0 + r + 8) * 72 + cbase + 2 * q) = *(unsigned*)&hi;
}

// one layer, one npair, TWO m-blocks sharing each B load; relu store
template <int KT>
__device__ __forceinline__ void layer2m16(const unsigned a0[][4], const unsigned a1[][4],
                                          const unsigned* B, int np, __half* dst,
                                          int rowM, int lane) {
    float c[4][4];
#pragma unroll
    for (int i = 0; i < 4; i++)
#pragma unroll
        for (int j = 0; j < 4; j++) c[i][j] = 0.f;
#pragma unroll
    for (int kt = 0; kt < KT; kt++) {
        uint4 b = *(const uint4*)(B + (kt * 4 + np) * 128 + lane * 4);
        mma16(c[0], a0[kt], b.x, b.y);
        mma16(c[1], a0[kt], b.z, b.w);
        mma16(c[2], a1[kt], b.x, b.y);
        mma16(c[3], a1[kt], b.z, b.w);
    }
    storeF16(dst, rowM, np * 16, lane,
             fmaxf(c[0][0], 0.f), fmaxf(c[0][1], 0.f), fmaxf(c[0][2], 0.f), fmaxf(c[0][3], 0.f));
    storeF16(dst, rowM, np * 16 + 8, lane,
             fmaxf(c[1][0], 0.f), fmaxf(c[1][1], 0.f), fmaxf(c[1][2], 0.f), fmaxf(c[1][3], 0.f));
    storeF16(dst, rowM + 16, np * 16, lane,
             fmaxf(c[2][0], 0.f), fmaxf(c[2][1], 0.f), fmaxf(c[2][2], 0.f), fmaxf(c[2][3], 0.f));
    storeF16(dst, rowM + 16, np * 16 + 8, lane,
             fmaxf(c[3][0], 0.f), fmaxf(c[3][1], 0.f), fmaxf(c[3][2], 0.f), fmaxf(c[3][3], 0.f));
}

// group barrier: 128 threads (4 warps), barrier id g+1 (2 groups)
#define GBAR() asm volatile("bar.sync %0, %1;" :: "r"(g + 1), "r"(128) : "memory")

__global__ void __launch_bounds__(256, 2)
nerf_mma(const float* __restrict__ x_feat, const float* __restrict__ dvec,
         const float* __restrict__ lvec, float* __restrict__ out,
         int N, int ntiles) {
    extern __shared__ float sm[];
    unsigned* sW = (unsigned*)sm;
    __half* B1   = (__half*)(sm + SM_B1);
    __half* B2   = (__half*)(sm + SM_B2);
    float* visP  = sm + SM_VISP;
    float* visR  = sm + SM_VISR;
    float* colP  = sm + SM_COLP;

    int tid = threadIdx.x, wid = tid >> 5, lane = tid & 31;
    int g = wid >> 2;               // 2 groups of 4 warps, 64 rows each
    int w4 = wid & 3;
    int mi = w4 >> 1, ni = w4 & 1;  // 2x2 warp grid
    int rowG = g * 64;
    int rowW = rowG + mi * 32;      // warp's 32 rows (2 m-blocks)
    int t2 = tid & 127;

    {
        const uint4* s = (const uint4*)g_W;
        uint4* d = (uint4*)sW;
        for (int i = tid; i < W_TOTAL / 4; i += 256) d[i] = s[i];
    }
    __syncthreads();

    for (int tile = blockIdx.x; tile < ntiles; tile += gridDim.x) {
        // ---- phase 0: fill group's 64 rows of B1 (x | l_enc | d_enc), f16 ----
        {
            if (t2 < 64) {
                int r = rowG + t2;
                int p = tile * 128 + r;
                int pc = (p < N) ? p : (N - 1);
                const float4* xp = (const float4*)(x_feat + 32 * (size_t)pc);
                unsigned* dst = (unsigned*)(B1 + r * 72);
#pragma unroll
                for (int i = 0; i < 8; i++) {
                    float4 v = xp[i];
                    __half2 h0 = __floats2half2_rn(v.x, v.y);
                    __half2 h1 = __floats2half2_rn(v.z, v.w);
                    dst[2 * i]     = *(unsigned*)&h0;
                    dst[2 * i + 1] = *(unsigned*)&h1;
                }
                float e[16];
                const float* dp = dvec + 3 * (size_t)pc;
                sh16(dp[0], dp[1], dp[2], e);
#pragma unroll
                for (int i = 0; i < 8; i++) {
                    __half2 h = __floats2half2_rn(e[2 * i], e[2 * i + 1]);
                    dst[24 + i] = *(unsigned*)&h;
                }
            } else {
                int r = rowG + t2 - 64;
                int p = tile * 128 + r;
                int pc = (p < N) ? p : (N - 1);
                float e[16];
                const float* lp = lvec + 3 * (size_t)pc;
                sh16(lp[0], lp[1], lp[2], e);
                unsigned* dst = (unsigned*)(B1 + r * 72);
#pragma unroll
                for (int i = 0; i < 8; i++) {
                    __half2 h = __floats2half2_rn(e[2 * i], e[2 * i + 1]);
                    dst[16 + i] = *(unsigned*)&h;
                }
            }
        }
        GBAR();

        // ---- phase 1: hoist A (8 frags), GBAR, sig0 / vis0(reg) / col0 ----
        {
            unsigned a0[4][4], a1[4][4];
#pragma unroll
            for (int kt = 0; kt < 4; kt++) {
                loadA16(a0[kt], B1 + rowW * 72, kt, lane);
                loadA16(a1[kt], B1 + (rowW + 16) * 72, kt, lane);
            }
            GBAR();     // hoists done; B1 stores now safe
            layer2m16<2>(a0, a1, sW + OFF_SIG0, 2 * ni,     B2, rowW, lane);
            layer2m16<2>(a0, a1, sW + OFF_SIG0, 2 * ni + 1, B2, rowW, lane);
            // vis0 in registers -> partial dot with w_vis1 (fp32)
            {
                float va[4] = {0.f, 0.f, 0.f, 0.f};
                const float* wv = (const float*)(sW + OFF_V1L);
#pragma unroll
                for (int npi = 0; npi < 2; npi++) {
                    int np = 2 * ni + npi;
                    float c[4][4];
#pragma unroll
                    for (int i = 0; i < 4; i++)
#pragma unroll
                        for (int j = 0; j < 4; j++) c[i][j] = 0.f;
#pragma unroll
                    for (int kt = 0; kt < 3; kt++) {
                        uint4 b = *(const uint4*)(sW + OFF_VIS0 + (kt * 4 + np) * 128 + lane * 4);
                        mma16(c[0], a0[kt], b.x, b.y);
                        mma16(c[1], a0[kt], b.z, b.w);
                        mma16(c[2], a1[kt], b.x, b.y);
                        mma16(c[3], a1[kt], b.z, b.w);
                    }
                    int q2 = 2 * (lane & 3);
                    float2 wA = *(const float2*)(wv + np * 16 + q2);
                    float2 wB = *(const float2*)(wv + np * 16 + 8 + q2);
                    va[0] += fmaxf(c[0][0], 0.f) * wA.x + fmaxf(c[0][1], 0.f) * wA.y
                           + fmaxf(c[1][0], 0.f) * wB.x + fmaxf(c[1][1], 0.f) * wB.y;
                    va[1] += fmaxf(c[0][2], 0.f) * wA.x + fmaxf(c[0][3], 0.f) * wA.y
                           + fmaxf(c[1][2], 0.f) * wB.x + fmaxf(c[1][3], 0.f) * wB.y;
                    va[2] += fmaxf(c[2][0], 0.f) * wA.x + fmaxf(c[2][1], 0.f) * wA.y
                           + fmaxf(c[3][0], 0.f) * wB.x + fmaxf(c[3][1], 0.f) * wB.y;
                    va[3] += fmaxf(c[2][2], 0.f) * wA.x + fmaxf(c[2][3], 0.f) * wA.y
                           + fmaxf(c[3][2], 0.f) * wB.x + fmaxf(c[3][3], 0.f) * wB.y;
                }
#pragma unroll
                for (int m = 1; m <= 2; m <<= 1) {
#pragma unroll
                    for (int i = 0; i < 4; i++)
                        va[i] += __shfl_xor_sync(0xffffffffu, va[i], m);
                }
                if ((lane & 3) == 0) {
                    int r = lane >> 2;
                    visP[(rowW + r) * 2 + ni]      = va[0];
                    visP[(rowW + r + 8) * 2 + ni]  = va[1];
                    visP[(rowW + 16 + r) * 2 + ni] = va[2];
                    visP[(rowW + 24 + r) * 2 + ni] = va[3];
                }
            }
            layer2m16<4>(a0, a1, sW + OFF_COL0, 2 * ni,     B1, rowW, lane);
            layer2m16<4>(a0, a1, sW + OFF_COL0, 2 * ni + 1, B1, rowW, lane);
        }
        GBAR();

        // ---- phase 2: warp = one 16-row block: sig1 -> geo; vis finalize ----
        {
            int rowB = rowG + w4 * 16;
            unsigned a[4][4];
#pragma unroll
            for (int kt = 0; kt < 4; kt++) loadA16(a[kt], B2 + rowB * 72, kt, lane);
            float c0[4] = {0.f, 0.f, 0.f, 0.f}, c1[4] = {0.f, 0.f, 0.f, 0.f};
#pragma unroll
            for (int kt = 0; kt < 4; kt++) {
                uint4 b = *(const uint4*)(sW + OFF_SIG1 + kt * 128 + lane * 4);
                mma16(c0, a[kt], b.x, b.y);
                mma16(c1, a[kt], b.z, b.w);
            }
            // geo: NO relu (f16 store rounds)
            storeF16(B2, rowB, 0, lane, c0[0], c0[1], c0[2], c0[3]);
            storeF16(B2, rowB, 8, lane, c1[0], c1[1], c1[2], c1[3]);
            if (t2 < 64) {
                int r = rowG + t2;
                float v = visP[2 * r] + visP[2 * r + 1];
                visR[r] = __fdividef(1.f, 1.f + __expf(-v));
            }
        }
        GBAR();

        // ---- phase 3: col1 = relu(col0_h @ C1A + geo @ C1B) -> B2 ----
        {
            unsigned a0[4][4], a1[4][4], g0[4], g1[4];
#pragma unroll
            for (int kt = 0; kt < 4; kt++) {
                loadA16(a0[kt], B1 + rowW * 72, kt, lane);
                loadA16(a1[kt], B1 + (rowW + 16) * 72, kt, lane);
            }
            loadA16(g0, B2 + rowW * 72, 0, lane);
            loadA16(g1, B2 + (rowW + 16) * 72, 0, lane);
            GBAR();     // hoists done; B2 stores now safe
#pragma unroll
            for (int npi = 0; npi < 2; npi++) {
                int np = 2 * ni + npi;
                float c[4][4];
#pragma unroll
                for (int i = 0; i < 4; i++)
#pragma unroll
                    for (int j = 0; j < 4; j++) c[i][j] = 0.f;
#pragma unroll
                for (int kt = 0; kt < 4; kt++) {
                    uint4 b = *(const uint4*)(sW + OFF_C1A + (kt * 4 + np) * 128 + lane * 4);
                    mma16(c[0], a0[kt], b.x, b.y);
                    mma16(c[1], a0[kt], b.z, b.w);
                    mma16(c[2], a1[kt], b.x, b.y);
                    mma16(c[3], a1[kt], b.z, b.w);
                }
                {
                    uint4 b = *(const uint4*)(sW + OFF_C1B + np * 128 + lane * 4);
                    mma16(c[0], g0, b.x, b.y);
                    mma16(c[1], g0, b.z, b.w);
                    mma16(c[2], g1, b.x, b.y);
                    mma16(c[3], g1, b.z, b.w);
                }
                storeF16(B2, rowW, np * 16, lane,
                         fmaxf(c[0][0], 0.f), fmaxf(c[0][1], 0.f),
                         fmaxf(c[0][2], 0.f), fmaxf(c[0][3], 0.f));
                storeF16(B2, rowW, np * 16 + 8, lane,
                         fmaxf(c[1][0], 0.f), fmaxf(c[1][1], 0.f),
                         fmaxf(c[1][2], 0.f), fmaxf(c[1][3], 0.f));
                storeF16(B2, rowW + 16, np * 16, lane,
                         fmaxf(c[2][0], 0.f), fmaxf(c[2][1], 0.f),
                         fmaxf(c[2][2], 0.f), fmaxf(c[2][3], 0.f));
                storeF16(B2, rowW + 16, np * 16 + 8, lane,
                         fmaxf(c[3][0], 0.f), fmaxf(c[3][1], 0.f),
                         fmaxf(c[3][2], 0.f), fmaxf(c[3][3], 0.f));
            }
        }
        GBAR();

        // ---- phase 4: col2: ni = k-half (kt 2 each); both m-blocks -> colP f32
        {
            int r = lane >> 2, q = lane & 3;
#pragma unroll
            for (int mb = 0; mb < 2; mb++) {
                int rb = rowW + mb * 16;
                unsigned a[2][4];
#pragma unroll
                for (int kt = 0; kt < 2; kt++)
                    loadA16(a[kt], B2 + rb * 72, ni * 2 + kt, lane);
                float c0[4] = {0.f, 0.f, 0.f, 0.f};
#pragma unroll
                for (int kt = 0; kt < 2; kt++) {
                    uint2 b = *(const uint2*)(sW + OFF_COL2 + (ni * 2 + kt) * 64 + lane * 2);
                    mma16(c0, a[kt], b.x, b.y);
                }
                *(float2*)(colP + (rb + r) * 16 + ni * 8 + 2 * q) = make_float2(c0[0], c0[1]);
                *(float2*)(colP + (rb + r + 8) * 16 + ni * 8 + 2 * q) = make_float2(c0[2], c0[3]);
            }
        }
        GBAR();

        // ---- epilogue: color = relu(p0+p1) * sigmoid(vis), group's 64 rows ----
        for (int i = t2; i < 192; i += 128) {
            int pp = rowG + i / 3, c = i % 3;
            int gg = tile * 128 + pp;
            if (gg < N) {
                float v = colP[pp * 16 + c] + colP[pp * 16 + 8 + c];
                out[3 * (size_t)gg + c] = fmaxf(v, 0.f) * visR[pp];
            }
        }
        GBAR();
    }
}

extern "C" void kernel_launch(void* const* d_in, const int* in_sizes, int n_in,
                              void* d_out, int out_size) {
    const float* x_feat = (const float*)d_in[0];
    const float* dv     = (const float*)d_in[1];
    const float* lv     = (const float*)d_in[2];
    const float* w_sig0 = (const float*)d_in[3];
    const float* w_sig1 = (const float*)d_in[4];
    const float* w_col0 = (const float*)d_in[5];
    const float* w_col1 = (const float*)d_in[6];
    const float* w_col2 = (const float*)d_in[7];
    const float* w_vis0 = (const float*)d_in[8];
    const float* w_vis1 = (const float*)d_in[9];
    float* out = (float*)d_out;
    int N = in_sizes[0] / 32;
    int ntiles = (N + 127) / 128;

    int dev = 0, smc = 148;
    cudaGetDevice(&dev);
    cudaDeviceGetAttribute(&smc, cudaDevAttrMultiProcessorCount, dev);
    int grid = (2 * smc < ntiles) ? 2 * smc : ntiles;

    cudaFuncSetAttribute(nerf_mma, cudaFuncAttributeMaxDynamicSharedMemorySize,
                         SMEM_BYTES);

    prep_kernel<<<1, 256>>>(w_sig0, w_sig1, w_col0, w_col1, w_col2, w_vis0, w_vis1);
    nerf_mma<<<grid, 256, SMEM_BYTES>>>(x_feat, dv, lv, out, N, ntiles);
}

// round 17
// speedup vs baseline: 1.1286x; 1.1286x over previous
#include <cuda_runtime.h>
#include <cuda_fp16.h>
#include <cstdint>

// ------------- weight layout in SMEM: f16 mma-fragment-packed (uints) ------
#define OFF_COL0 0          // 4 kt x 4 np
#define OFF_VIS0 2048       // 3 x 4
#define OFF_SIG0 3584       // 2 x 4
#define OFF_C1A  4608       // 4 x 4
#define OFF_C1B  6656       // 1 x 4 (k row0 zero, rows 1..15 = col1 rows 64..78)
#define OFF_SIG1 7168       // 4 kt x 1 np
#define OFF_COL2 7680       // 4 kt x 64 uints (single n8, n<3 real)
#define OFF_V1L  7936       // 64 f32 (vis1 weights, stored as bits)
#define W_TOTAL  8192

// ---------------- SH degree-4 ----------------
__device__ __forceinline__ void sh16(float x, float y, float z, float* e) {
    float xx = x * x, yy = y * y, zz = z * z;
    float xy = x * y, yz = y * z, xz = x * z;
    e[0]  = 0.28209479177387814f;
    e[1]  = -0.48860251190291987f * y;
    e[2]  = 0.48860251190291987f * z;
    e[3]  = -0.48860251190291987f * x;
    e[4]  = 1.0925484305920792f * xy;
    e[5]  = -1.0925484305920792f * yz;
    e[6]  = 0.94617469575756f * zz - 0.31539156525252005f;
    e[7]  = -1.0925484305920792f * xz;
    e[8]  = 0.5462742152960396f * (xx - yy);
    e[9]  = 0.5900435899266435f * y * (3.0f * xx - yy);
    e[10] = 2.890611442640554f * xy * z;
    e[11] = 0.4570457994644657f * y * (4.0f * zz - xx - yy);
    e[12] = 0.3731763325901154f * z * (2.0f * zz - 3.0f * xx - 3.0f * yy);
    e[13] = 0.4570457994644657f * x * (4.0f * zz - xx - yy);
    e[14] = 1.445305721320277f * z * (xx - yy);
    e[15] = 0.5900435899266435f * x * (xx - 3.0f * yy);
}

// ---- smem layout (float indices): weights 8192, then f16 row-buffers -----
#define SM_B1    8192               // [256][72] halfs = 9216 floats
#define SM_B2    17408              // [256][72] halfs
#define SM_VISP  26624              // [256][2] f32
#define SM_VISR  27136              // [256] f32
#define SM_COLP  27392              // [256][16] f32
#define SM_TOTAL 31488
#define SMEM_BYTES (SM_TOTAL * 4)

// in-kernel weight packing (writes CTA's SMEM directly)
__device__ void packB16s(unsigned* dst, const float* W, int Kreal, int Nreal,
                         int KT, int NP, int t, int st) {
    for (int idx = t; idx < KT * NP * 128; idx += st) {
        int blk = idx >> 7, w = idx & 127;
        int lane = w >> 2, j2 = w & 3;
        int j = j2 >> 1, which = j2 & 1;
        int kt = blk / NP, np = blk % NP;
        int r = lane >> 2, q = lane & 3;
        int n = np * 16 + j * 8 + r;
        int k0 = kt * 16 + 2 * q + which * 8;
        float v0 = (k0 < Kreal && n < Nreal) ? W[k0 * Nreal + n] : 0.f;
        float v1 = (k0 + 1 < Kreal && n < Nreal) ? W[(k0 + 1) * Nreal + n] : 0.f;
        __half2 h = __floats2half2_rn(v0, v1);
        dst[idx] = *(unsigned*)&h;
    }
}

// ---------------- raw f16 mma helpers ----------------
__device__ __forceinline__ void mma16(float* c, const unsigned* a, unsigned b0, unsigned b1) {
    asm volatile(
        "mma.sync.aligned.m16n8k16.row.col.f32.f16.f16.f32 "
        "{%0,%1,%2,%3}, {%4,%5,%6,%7}, {%8,%9}, {%0,%1,%2,%3};"
        : "+f"(c[0]), "+f"(c[1]), "+f"(c[2]), "+f"(c[3])
        : "r"(a[0]), "r"(a[1]), "r"(a[2]), "r"(a[3]), "r"(b0), "r"(b1));
}

// A fragment via ldmatrix.x4: one instruction per (16-row block, kt)
__device__ __forceinline__ void ldmA(unsigned* a, const __half* Ab, int kt, int lane) {
    const __half* p = Ab + (lane & 15) * 72 + kt * 16 + ((lane >> 4) << 3);
    unsigned addr = (unsigned)__cvta_generic_to_shared(p);
    asm volatile("ldmatrix.sync.aligned.m8n8.x4.shared.b16 {%0,%1,%2,%3}, [%4];"
                 : "=r"(a[0]), "=r"(a[1]), "=r"(a[2]), "=r"(a[3]) : "r"(addr));
}

__device__ __forceinline__ void storeF16(__half* dst, int row0, int cbase, int lane,
                                         float c0, float c1, float c2, float c3) {
    int r = lane >> 2, q = lane & 3;
    __half2 lo = __floats2half2_rn(c0, c1);
    __half2 hi = __floats2half2_rn(c2, c3);
    *(unsigned*)(dst + (row0 + r) * 72 + cbase + 2 * q) = *(unsigned*)&lo;
    *(unsigned*)(dst + (row0 + r + 8) * 72 + cbase + 2 * q) = *(unsigned*)&hi;
}

// one layer, one npair, TWO m-blocks sharing each B load; relu store
template <int KT>
__device__ __forceinline__ void layer2m16(const unsigned a0[][4], const unsigned a1[][4],
                                          const unsigned* B, int np, __half* dst,
                                          int rowM, int lane) {
    float c[4][4];
#pragma unroll
    for (int i = 0; i < 4; i++)
#pragma unroll
        for (int j = 0; j < 4; j++) c[i][j] = 0.f;
#pragma unroll
    for (int kt = 0; kt < KT; kt++) {
        uint4 b = *(const uint4*)(B + (kt * 4 + np) * 128 + lane * 4);
        mma16(c[0], a0[kt], b.x, b.y);
        mma16(c[1], a0[kt], b.z, b.w);
        mma16(c[2], a1[kt], b.x, b.y);
        mma16(c[3], a1[kt], b.z, b.w);
    }
    storeF16(dst, rowM, np * 16, lane,
             fmaxf(c[0][0], 0.f), fmaxf(c[0][1], 0.f), fmaxf(c[0][2], 0.f), fmaxf(c[0][3], 0.f));
    storeF16(dst, rowM, np * 16 + 8, lane,
             fmaxf(c[1][0], 0.f), fmaxf(c[1][1], 0.f), fmaxf(c[1][2], 0.f), fmaxf(c[1][3], 0.f));
    storeF16(dst, rowM + 16, np * 16, lane,
             fmaxf(c[2][0], 0.f), fmaxf(c[2][1], 0.f), fmaxf(c[2][2], 0.f), fmaxf(c[2][3], 0.f));
    storeF16(dst, rowM + 16, np * 16 + 8, lane,
             fmaxf(c[3][0], 0.f), fmaxf(c[3][1], 0.f), fmaxf(c[3][2], 0.f), fmaxf(c[3][3], 0.f));
}

// group barrier: 128 threads (4 warps), barrier id g+1 (4 groups)
#define GBAR() asm volatile("bar.sync %0, %1;" :: "r"(g + 1), "r"(128) : "memory")

__global__ void __launch_bounds__(512, 1)
nerf_mma(const float* __restrict__ x_feat, const float* __restrict__ dvec,
         const float* __restrict__ lvec, float* __restrict__ out,
         const float* __restrict__ ws0, const float* __restrict__ ws1,
         const float* __restrict__ wc0, const float* __restrict__ wc1,
         const float* __restrict__ wc2, const float* __restrict__ wv0,
         const float* __restrict__ wv1,
         int N, int ntiles) {
    extern __shared__ float sm[];
    unsigned* sW = (unsigned*)sm;
    __half* B1   = (__half*)(sm + SM_B1);
    __half* B2   = (__half*)(sm + SM_B2);
    float* visP  = sm + SM_VISP;
    float* visR  = sm + SM_VISR;
    float* colP  = sm + SM_COLP;

    int tid = threadIdx.x, wid = tid >> 5, lane = tid & 31;
    int g = wid >> 2;               // 4 groups of 4 warps, 64 rows each
    int w4 = wid & 3;
    int mi = w4 >> 1, ni = w4 & 1;  // 2x2 warp grid
    int rowG = g * 64;
    int rowW = rowG + mi * 32;      // warp's 32 rows (2 m-blocks)
    int t2 = tid & 127;

    // ---- one-time per-CTA weight packing straight from gmem ----
    packB16s(sW + OFF_COL0, wc0, 64, 64, 4, 4, tid, 512);
    packB16s(sW + OFF_VIS0, wv0, 48, 64, 3, 4, tid, 512);
    packB16s(sW + OFF_SIG0, ws0, 32, 64, 2, 4, tid, 512);
    packB16s(sW + OFF_C1A,  wc1, 64, 64, 4, 4, tid, 512);
    packB16s(sW + OFF_SIG1, ws1, 64, 16, 4, 1, tid, 512);
    if (tid < 512) {
        int idx = tid;              // C1B: 512 uints exactly
        int w = idx & 127;
        int lane2 = w >> 2, j2 = w & 3;
        int j = j2 >> 1, which = j2 & 1;
        int np = idx >> 7;
        int r = lane2 >> 2, q = lane2 & 3;
        int n = np * 16 + j * 8 + r;
        int k0 = 2 * q + which * 8;
        float v0 = (k0 >= 1 && k0 < 16) ? wc1[(63 + k0) * 64 + n] : 0.f;
        float v1 = (k0 + 1 >= 1 && k0 + 1 < 16) ? wc1[(63 + k0 + 1) * 64 + n] : 0.f;
        __half2 h = __floats2half2_rn(v0, v1);
        sW[OFF_C1B + idx] = *(unsigned*)&h;
    }
    if (tid < 256) {                // COL2: 256 uints
        int idx = tid;
        int kt = idx >> 6, w = idx & 63;
        int lane2 = w >> 1, which = w & 1;
        int r = lane2 >> 2, q = lane2 & 3;
        int n = r;
        int k0 = kt * 16 + 2 * q + which * 8;
        float v0 = (n < 3) ? wc2[k0 * 3 + n] : 0.f;
        float v1 = (n < 3) ? wc2[(k0 + 1) * 3 + n] : 0.f;
        __half2 h = __floats2half2_rn(v0, v1);
        sW[OFF_COL2 + idx] = *(unsigned*)&h;
    }
    if (tid < 64) sW[OFF_V1L + tid] = __float_as_uint(wv1[tid]);
    __syncthreads();

    for (int tile = blockIdx.x; tile < ntiles; tile += gridDim.x) {
        // ---- phase 0: fill group's 64 rows of B1 (x | l_enc | d_enc), f16 ----
        {
            if (t2 < 64) {
                int r = rowG + t2;
                int p = tile * 256 + r;
                int pc = (p < N) ? p : (N - 1);
                const float4* xp = (const float4*)(x_feat + 32 * (size_t)pc);
                unsigned* dst = (unsigned*)(B1 + r * 72);
#pragma unroll
                for (int i = 0; i < 8; i++) {
                    float4 v = xp[i];
                    __half2 h0 = __floats2half2_rn(v.x, v.y);
                    __half2 h1 = __floats2half2_rn(v.z, v.w);
                    dst[2 * i]     = *(unsigned*)&h0;
                    dst[2 * i + 1] = *(unsigned*)&h1;
                }
                float e[16];
                const float* dp = dvec + 3 * (size_t)pc;
                sh16(dp[0], dp[1], dp[2], e);
#pragma unroll
                for (int i = 0; i < 8; i++) {
                    __half2 h = __floats2half2_rn(e[2 * i], e[2 * i + 1]);
                    dst[24 + i] = *(unsigned*)&h;
                }
            } else {
                int r = rowG + t2 - 64;
                int p = tile * 256 + r;
                int pc = (p < N) ? p : (N - 1);
                float e[16];
                const float* lp = lvec + 3 * (size_t)pc;
                sh16(lp[0], lp[1], lp[2], e);
                unsigned* dst = (unsigned*)(B1 + r * 72);
#pragma unroll
                for (int i = 0; i < 8; i++) {
                    __half2 h = __floats2half2_rn(e[2 * i], e[2 * i + 1]);
                    dst[16 + i] = *(unsigned*)&h;
                }
            }
        }
        GBAR();

        // ---- phase 1: hoist A via ldmatrix, GBAR, sig0 / vis0(reg) / col0 ----
        {
            unsigned a0[4][4], a1[4][4];
#pragma unroll
            for (int kt = 0; kt < 4; kt++) {
                ldmA(a0[kt], B1 + rowW * 72, kt, lane);
                ldmA(a1[kt], B1 + (rowW + 16) * 72, kt, lane);
            }
            GBAR();     // hoists done; B1 stores now safe
            layer2m16<2>(a0, a1, sW + OFF_SIG0, 2 * ni,     B2, rowW, lane);
            layer2m16<2>(a0, a1, sW + OFF_SIG0, 2 * ni + 1, B2, rowW, lane);
            // vis0 in registers -> partial dot with w_vis1 (fp32)
            {
                float va[4] = {0.f, 0.f, 0.f, 0.f};
                const float* wv = (const float*)(sW + OFF_V1L);
#pragma unroll
                for (int npi = 0; npi < 2; npi++) {
                    int np = 2 * ni + npi;
                    float c[4][4];
#pragma unroll
                    for (int i = 0; i < 4; i++)
#pragma unroll
                        for (int j = 0; j < 4; j++) c[i][j] = 0.f;
#pragma unroll
                    for (int kt = 0; kt < 3; kt++) {
                        uint4 b = *(const uint4*)(sW + OFF_VIS0 + (kt * 4 + np) * 128 + lane * 4);
                        mma16(c[0], a0[kt], b.x, b.y);
                        mma16(c[1], a0[kt], b.z, b.w);
                        mma16(c[2], a1[kt], b.x, b.y);
                        mma16(c[3], a1[kt], b.z, b.w);
                    }
                    int q2 = 2 * (lane & 3);
                    float2 wA = *(const float2*)(wv + np * 16 + q2);
                    float2 wB = *(const float2*)(wv + np * 16 + 8 + q2);
                    va[0] += fmaxf(c[0][0], 0.f) * wA.x + fmaxf(c[0][1], 0.f) * wA.y
                           + fmaxf(c[1][0], 0.f) * wB.x + fmaxf(c[1][1], 0.f) * wB.y;
                    va[1] += fmaxf(c[0][2], 0.f) * wA.x + fmaxf(c[0][3], 0.f) * wA.y
                           + fmaxf(c[1][2], 0.f) * wB.x + fmaxf(c[1][3], 0.f) * wB.y;
                    va[2] += fmaxf(c[2][0], 0.f) * wA.x + fmaxf(c[2][1], 0.f) * wA.y
                           + fmaxf(c[3][0], 0.f) * wB.x + fmaxf(c[3][1], 0.f) * wB.y;
                    va[3] += fmaxf(c[2][2], 0.f) * wA.x + fmaxf(c[2][3], 0.f) * wA.y
                           + fmaxf(c[3][2], 0.f) * wB.x + fmaxf(c[3][3], 0.f) * wB.y;
                }
#pragma unroll
                for (int m = 1; m <= 2; m <<= 1) {
#pragma unroll
                    for (int i = 0; i < 4; i++)
                        va[i] += __shfl_xor_sync(0xffffffffu, va[i], m);
                }
                if ((lane & 3) == 0) {
                    int r = lane >> 2;
                    visP[(rowW + r) * 2 + ni]      = va[0];
                    visP[(rowW + r + 8) * 2 + ni]  = va[1];
                    visP[(rowW + 16 + r) * 2 + ni] = va[2];
                    visP[(rowW + 24 + r) * 2 + ni] = va[3];
                }
            }
            layer2m16<4>(a0, a1, sW + OFF_COL0, 2 * ni,     B1, rowW, lane);
            layer2m16<4>(a0, a1, sW + OFF_COL0, 2 * ni + 1, B1, rowW, lane);
        }
        GBAR();

        // ---- phase 2: warp = one 16-row block: sig1 -> geo; vis finalize ----
        {
            int rowB = rowG + w4 * 16;
            unsigned a[4][4];
#pragma unroll
            for (int kt = 0; kt < 4; kt++) ldmA(a[kt], B2 + rowB * 72, kt, lane);
            float c0[4] = {0.f, 0.f, 0.f, 0.f}, c1[4] = {0.f, 0.f, 0.f, 0.f};
#pragma unroll
            for (int kt = 0; kt < 4; kt++) {
                uint4 b = *(const uint4*)(sW + OFF_SIG1 + kt * 128 + lane * 4);
                mma16(c0, a[kt], b.x, b.y);
                mma16(c1, a[kt], b.z, b.w);
            }
            // geo: NO relu (f16 store rounds)
            storeF16(B2, rowB, 0, lane, c0[0], c0[1], c0[2], c0[3]);
            storeF16(B2, rowB, 8, lane, c1[0], c1[1], c1[2], c1[3]);
            if (t2 < 64) {
                int r = rowG + t2;
                float v = visP[2 * r] + visP[2 * r + 1];
                visR[r] = __fdividef(1.f, 1.f + __expf(-v));
            }
        }
        GBAR();

        // ---- phase 3: col1 = relu(col0_h @ C1A + geo @ C1B) -> B2 ----
        {
            unsigned a0[4][4], a1[4][4], g0[4], g1[4];
#pragma unroll
            for (int kt = 0; kt < 4; kt++) {
                ldmA(a0[kt], B1 + rowW * 72, kt, lane);
                ldmA(a1[kt], B1 + (rowW + 16) * 72, kt, lane);
            }
            ldmA(g0, B2 + rowW * 72, 0, lane);
            ldmA(g1, B2 + (rowW + 16) * 72, 0, lane);
            GBAR();     // hoists done; B2 stores now safe
#pragma unroll
            for (int npi = 0; npi < 2; npi++) {
                int np = 2 * ni + npi;
                float c[4][4];
#pragma unroll
                for (int i = 0; i < 4; i++)
#pragma unroll
                    for (int j = 0; j < 4; j++) c[i][j] = 0.f;
#pragma unroll
                for (int kt = 0; kt < 4; kt++) {
                    uint4 b = *(const uint4*)(sW + OFF_C1A + (kt * 4 + np) * 128 + lane * 4);
                    mma16(c[0], a0[kt], b.x, b.y);
                    mma16(c[1], a0[kt], b.z, b.w);
                    mma16(c[2], a1[kt], b.x, b.y);
                    mma16(c[3], a1[kt], b.z, b.w);
                }
                {
                    uint4 b = *(const uint4*)(sW + OFF_C1B + np * 128 + lane * 4);
                    mma16(c[0], g0, b.x, b.y);
                    mma16(c[1], g0, b.z, b.w);
                    mma16(c[2], g1, b.x, b.y);
                    mma16(c[3], g1, b.z, b.w);
                }
                storeF16(B2, rowW, np * 16, lane,
                         fmaxf(c[0][0], 0.f), fmaxf(c[0][1], 0.f),
                         fmaxf(c[0][2], 0.f), fmaxf(c[0][3], 0.f));
                storeF16(B2, rowW, np * 16 + 8, lane,
                         fmaxf(c[1][0], 0.f), fmaxf(c[1][1], 0.f),
                         fmaxf(c[1][2], 0.f), fmaxf(c[1][3], 0.f));
                storeF16(B2, rowW + 16, np * 16, lane,
                         fmaxf(c[2][0], 0.f), fmaxf(c[2][1], 0.f),
                         fmaxf(c[2][2], 0.f), fmaxf(c[2][3], 0.f));
                storeF16(B2, rowW + 16, np * 16 + 8, lane,
                         fmaxf(c[3][0], 0.f), fmaxf(c[3][1], 0.f),
                         fmaxf(c[3][2], 0.f), fmaxf(c[3][3], 0.f));
            }
        }
        GBAR();

        // ---- phase 4: col2: ni = k-half (kt 2 each); both m-blocks -> colP f32
        {
            int r = lane >> 2, q = lane & 3;
#pragma unroll
            for (int mb = 0; mb < 2; mb++) {
                int rb = rowW + mb * 16;
                unsigned a[2][4];
#pragma unroll
                for (int kt = 0; kt < 2; kt++)
                    ldmA(a[kt], B2 + rb * 72, ni * 2 + kt, lane);
                float c0[4] = {0.f, 0.f, 0.f, 0.f};
#pragma unroll
                for (int kt = 0; kt < 2; kt++) {
                    uint2 b = *(const uint2*)(sW + OFF_COL2 + (ni * 2 + kt) * 64 + lane * 2);
                    mma16(c0, a[kt], b.x, b.y);
                }
                *(float2*)(colP + (rb + r) * 16 + ni * 8 + 2 * q) = make_float2(c0[0], c0[1]);
                *(float2*)(colP + (rb + r + 8) * 16 + ni * 8 + 2 * q) = make_float2(c0[2], c0[3]);
            }
        }
        GBAR();

        // ---- epilogue: color = relu(p0+p1) * sigmoid(vis), group's 64 rows ----
        for (int i = t2; i < 192; i += 128) {
            int pp = rowG + i / 3, c = i % 3;
            int gg = tile * 256 + pp;
            if (gg < N) {
                float v = colP[pp * 16 + c] + colP[pp * 16 + 8 + c];
                out[3 * (size_t)gg + c] = fmaxf(v, 0.f) * visR[pp];
            }
        }
        GBAR();
    }
}

extern "C" void kernel_launch(void* const* d_in, const int* in_sizes, int n_in,
                              void* d_out, int out_size) {
    const float* x_feat = (const float*)d_in[0];
    const float* dv     = (const float*)d_in[1];
    const float* lv     = (const float*)d_in[2];
    const float* w_sig0 = (const float*)d_in[3];
    const float* w_sig1 = (const float*)d_in[4];
    const float* w_col0 = (const float*)d_in[5];
    const float* w_col1 = (const float*)d_in[6];
    const float* w_col2 = (const float*)d_in[7];
    const float* w_vis0 = (const float*)d_in[8];
    const float* w_vis1 = (const float*)d_in[9];
    float* out = (float*)d_out;
    int N = in_sizes[0] / 32;
    int ntiles = (N + 255) / 256;

    int dev = 0, smc = 148;
    cudaGetDevice(&dev);
    cudaDeviceGetAttribute(&smc, cudaDevAttrMultiProcessorCount, dev);
    int grid = (smc < ntiles) ? smc : ntiles;

    cudaFuncSetAttribute(nerf_mma, cudaFuncAttributeMaxDynamicSharedMemorySize,
                         SMEM_BYTES);

    nerf_mma<<<grid, 512, SMEM_BYTES>>>(x_feat, dv, lv, out,
                                        w_sig0, w_sig1, w_col0, w_col1, w_col2,
                                        w_vis0, w_vis1, N, ntiles);
}